// round 5
// baseline (speedup 1.0000x reference)
#include <cuda_runtime.h>
#include <cstdint>

// Problem constants (fixed by the reference)
#define VOCAB 32000
#define D_EMB 768
#define SEQ   2048
#define BATCH 16
#define F4_PER_ROW (D_EMB / 4)   // 192

// Device scratch for the two precombined D-vectors (no cudaMalloc allowed).
__device__ float g_tok0[D_EMB];
__device__ float g_seg0[D_EMB];

// ---------------------------------------------------------------------------
// Prep: tok0[d] = W_tok[d, 0] + b_tok[d]   (W_tok is [D, VOCAB] row-major)
//       seg0[d] = W_seg[d, 0] + b_seg[d]   (W_seg is [D, 3]     row-major)
// One block of 768 threads; negligible cost.
// ---------------------------------------------------------------------------
__global__ void bebert_prep_kernel(const float* __restrict__ W_tok,
                                   const float* __restrict__ b_tok,
                                   const float* __restrict__ W_seg,
                                   const float* __restrict__ b_seg) {
    int d = threadIdx.x;
    if (d < D_EMB) {
        g_tok0[d] = W_tok[(size_t)d * VOCAB] + b_tok[d];
        g_seg0[d] = W_seg[(size_t)d * 3]     + b_seg[d];
    }
}

// ---------------------------------------------------------------------------
// Main: one block per sequence position s (2048 blocks), 192 threads.
// Each thread owns one float4 of the D dimension, keeps pe/tok0/seg0 in
// registers, and loops over the 16 batch rows → 16 coalesced float4 stores.
// DRAM traffic ≈ 100.7 MB write + ~6.5 MB read  → write-stream bound.
// ---------------------------------------------------------------------------
__global__ void __launch_bounds__(F4_PER_ROW)
bebert_embed_kernel(const int* __restrict__ input_ids,
                    const int* __restrict__ segment_label,
                    const float* __restrict__ pe,
                    float* __restrict__ out) {
    const int s = blockIdx.x;    // 0..SEQ-1
    const int t = threadIdx.x;   // 0..191 (float4 index within row)

    // pe is [1, SEQ, D]; row s
    const float4 p  = reinterpret_cast<const float4*>(pe + (size_t)s * D_EMB)[t];
    const float4 tv = reinterpret_cast<const float4*>(g_tok0)[t];
    const float4 sv = reinterpret_cast<const float4*>(g_seg0)[t];

    float4* out4 = reinterpret_cast<float4*>(out);

#pragma unroll
    for (int b = 0; b < BATCH; ++b) {
        const int row = b * SEQ + s;
        const bool tok_hit = (__ldg(input_ids     + row) == 0);  // warp-uniform
        const bool seg_hit = (__ldg(segment_label + row) == 0);  // warp-uniform

        float4 r = p;
        if (tok_hit) { r.x += tv.x; r.y += tv.y; r.z += tv.z; r.w += tv.w; }
        if (seg_hit) { r.x += sv.x; r.y += sv.y; r.z += sv.z; r.w += sv.w; }

        out4[(size_t)row * F4_PER_ROW + t] = r;
    }
}

// ---------------------------------------------------------------------------
// Launch. Input order (metadata): input_ids, segment_label, W_tok, b_tok,
// W_seg, b_seg, pe. ids arrive as int32 (jax x64 disabled). Output fp32.
// ---------------------------------------------------------------------------
extern "C" void kernel_launch(void* const* d_in, const int* in_sizes, int n_in,
                              void* d_out, int out_size) {
    const int*   input_ids     = (const int*)  d_in[0];
    const int*   segment_label = (const int*)  d_in[1];
    const float* W_tok         = (const float*)d_in[2];
    const float* b_tok         = (const float*)d_in[3];
    const float* W_seg         = (const float*)d_in[4];
    const float* b_seg         = (const float*)d_in[5];
    const float* pe            = (const float*)d_in[6];
    float*       out           = (float*)d_out;

    bebert_prep_kernel<<<1, D_EMB>>>(W_tok, b_tok, W_seg, b_seg);
    bebert_embed_kernel<<<SEQ, F4_PER_ROW>>>(input_ids, segment_label, pe, out);
}

// round 6
// speedup vs baseline: 1.1001x; 1.1001x over previous
#include <cuda_runtime.h>
#include <cstdint>

// Problem constants (fixed by the reference)
#define VOCAB 32000
#define D_EMB 768
#define SEQ   2048
#define BATCH 16
#define F4    (D_EMB / 4)              // 192 float4 per row
#define ROWS_PER_BLK 2
#define THREADS (F4 * ROWS_PER_BLK)    // 384

// ---------------------------------------------------------------------------
// Fused kernel. Semantics (from the reference's where() inversion):
//   out[b,s,d] = pe[s,d]
//              + (input_ids[b,s]==0     ? W_tok[d,0]+b_tok[d] : 0)
//              + (segment_label[b,s]==0 ? W_seg[d,0]+b_seg[d] : 0)
//
// One block handles ROWS_PER_BLK consecutive s values. The block first
// rebuilds the two combined D-vectors in shared memory (strided column-0
// gather: DRAM once, L2 hits for the remaining 1023 blocks), and 32 threads
// cooperatively load the 2x16x2 ids into a small mask table — eliminating the
// 6144 redundant warp-uniform LDGs/block the previous version issued.
// Then each thread owns one (s, float4-column), keeps pe/tok/seg in
// registers, and streams 16 coalesced float4 stores (one per batch row).
// ---------------------------------------------------------------------------
__global__ void __launch_bounds__(THREADS)
bebert_fused_kernel(const int*   __restrict__ input_ids,
                    const int*   __restrict__ segment_label,
                    const float* __restrict__ W_tok,
                    const float* __restrict__ b_tok,
                    const float* __restrict__ W_seg,
                    const float* __restrict__ b_seg,
                    const float* __restrict__ pe,
                    float*       __restrict__ out)
{
    __shared__ __align__(16) float s_tok[D_EMB];
    __shared__ __align__(16) float s_seg[D_EMB];
    __shared__ int s_mask[ROWS_PER_BLK][BATCH];

    const int t  = threadIdx.x;
    const int s0 = blockIdx.x * ROWS_PER_BLK;

    // --- prep: combined vectors into smem (2 elements per thread) ---
#pragma unroll
    for (int d = t; d < D_EMB; d += THREADS) {
        s_tok[d] = __ldg(W_tok + (size_t)d * VOCAB) + __ldg(b_tok + d);
        s_seg[d] = __ldg(W_seg + (size_t)d * 3)     + __ldg(b_seg + d);
    }

    // --- cooperative id -> mask load (32 threads, 64 LDG total) ---
    if (t < ROWS_PER_BLK * BATCH) {
        const int local = t / BATCH;              // which s in this block
        const int b     = t % BATCH;
        const int row   = b * SEQ + s0 + local;
        const int m = (__ldg(input_ids     + row) == 0 ? 1 : 0)
                    | (__ldg(segment_label + row) == 0 ? 2 : 0);
        s_mask[local][b] = m;
    }
    __syncthreads();

    const int local = t / F4;                     // 0..ROWS_PER_BLK-1
    const int c     = t % F4;                     // float4 column
    const int s     = s0 + local;

    const float4 p  = reinterpret_cast<const float4*>(pe + (size_t)s * D_EMB)[c];
    const float4 tv = reinterpret_cast<const float4*>(s_tok)[c];
    const float4 sv = reinterpret_cast<const float4*>(s_seg)[c];

    float4* out4 = reinterpret_cast<float4*>(out) + (size_t)s * F4 + c;

#pragma unroll
    for (int b = 0; b < BATCH; ++b) {
        const int m = s_mask[local][b];           // smem broadcast
        float4 r = p;
        if (m & 1) { r.x += tv.x; r.y += tv.y; r.z += tv.z; r.w += tv.w; }
        if (m & 2) { r.x += sv.x; r.y += sv.y; r.z += sv.z; r.w += sv.w; }
        out4[(size_t)b * (SEQ * F4)] = r;         // stride 6 MB between batch rows
    }
}

// ---------------------------------------------------------------------------
// Launch. Input order (metadata): input_ids, segment_label, W_tok, b_tok,
// W_seg, b_seg, pe. ids arrive as int32 (jax x64 disabled). Output fp32.
// Single kernel launch — no prep kernel, no inter-launch gap.
// ---------------------------------------------------------------------------
extern "C" void kernel_launch(void* const* d_in, const int* in_sizes, int n_in,
                              void* d_out, int out_size) {
    const int*   input_ids     = (const int*)  d_in[0];
    const int*   segment_label = (const int*)  d_in[1];
    const float* W_tok         = (const float*)d_in[2];
    const float* b_tok         = (const float*)d_in[3];
    const float* W_seg         = (const float*)d_in[4];
    const float* b_seg         = (const float*)d_in[5];
    const float* pe            = (const float*)d_in[6];
    float*       out           = (float*)d_out;

    bebert_fused_kernel<<<SEQ / ROWS_PER_BLK, THREADS>>>(
        input_ids, segment_label, W_tok, b_tok, W_seg, b_seg, pe, out);
}